// round 1
// baseline (speedup 1.0000x reference)
#include <cuda_runtime.h>
#include <math.h>

// Problem constants
#define B_  4
#define S_  2048
#define H_  1024
#define NH_ 16
#define HD_ 64
#define M_  (B_ * S_)          // 8192 rows for projection GEMMs
#define SCALE_INV 0.125f       // 1/sqrt(64)
#define NEGBIG   -1e10f

// Scratch (device globals — no allocation allowed)
__device__ float g_Q[M_ * H_];   // [B, NH, S, HD] head-split
__device__ float g_K[M_ * H_];
__device__ float g_V[M_ * H_];
__device__ float g_X[M_ * H_];   // [B, S, H] (heads re-merged)

// ---------------------------------------------------------------------------
// Projection GEMM: C[m,n] = sum_k A[m,k] * W[n,k] + bias[n]
// A: [M_, 1024] row-major; W: [1024, 1024] row-major (n-major rows, k contig)
// split==1 -> write head-split layout [B, NH, S, HD]; else flat [M_, H_]
// ---------------------------------------------------------------------------
__global__ void gemm_proj(const float* __restrict__ A,
                          const float* __restrict__ W,
                          const float* __restrict__ bias,
                          float* __restrict__ out, int split) {
    __shared__ float As[64][33];
    __shared__ float Ws[64][33];
    const int bm = blockIdx.y * 64;
    const int bn = blockIdx.x * 64;
    const int tx = threadIdx.x, ty = threadIdx.y;
    const int tid = ty * 16 + tx;

    float acc[4][4] = {};
    for (int k0 = 0; k0 < H_; k0 += 32) {
        #pragma unroll
        for (int i = tid; i < 64 * 32; i += 256) {
            int r = i >> 5, c = i & 31;
            As[r][c] = A[(size_t)(bm + r) * H_ + k0 + c];
            Ws[r][c] = W[(size_t)(bn + r) * H_ + k0 + c];
        }
        __syncthreads();
        #pragma unroll
        for (int kk = 0; kk < 32; kk++) {
            float a[4], w[4];
            #pragma unroll
            for (int i = 0; i < 4; i++) a[i] = As[ty * 4 + i][kk];
            #pragma unroll
            for (int j = 0; j < 4; j++) w[j] = Ws[tx * 4 + j][kk];
            #pragma unroll
            for (int i = 0; i < 4; i++)
                #pragma unroll
                for (int j = 0; j < 4; j++)
                    acc[i][j] = fmaf(a[i], w[j], acc[i][j]);
        }
        __syncthreads();
    }

    #pragma unroll
    for (int i = 0; i < 4; i++) {
        int m = bm + ty * 4 + i;
        #pragma unroll
        for (int j = 0; j < 4; j++) {
            int n = bn + tx * 4 + j;
            float v = acc[i][j] + bias[n];
            if (split) {
                int b = m / S_, s = m % S_;
                int h = n / HD_, d = n % HD_;
                out[(((size_t)(b * NH_ + h) * S_) + s) * HD_ + d] = v;
            } else {
                out[(size_t)m * H_ + n] = v;
            }
        }
    }
}

// ---------------------------------------------------------------------------
// Energy: per (b,h): E[q,k] = (Q[q,:] . K[k,:]) / 8, masked -> attn buffer
// ---------------------------------------------------------------------------
__global__ void energy_kernel(const int* __restrict__ mask,
                              float* __restrict__ attn) {
    __shared__ float Qs[64][65];
    __shared__ float Ks[64][65];
    const int bh = blockIdx.z;
    const int b = bh / NH_;
    const int bq = blockIdx.y * 64;
    const int bk = blockIdx.x * 64;
    const int tx = threadIdx.x, ty = threadIdx.y;
    const int tid = ty * 16 + tx;

    const float* Qb = g_Q + (size_t)bh * S_ * HD_;
    const float* Kb = g_K + (size_t)bh * S_ * HD_;

    #pragma unroll
    for (int i = tid; i < 64 * 64; i += 256) {
        int r = i >> 6, c = i & 63;
        Qs[r][c] = Qb[(size_t)(bq + r) * HD_ + c];
        Ks[r][c] = Kb[(size_t)(bk + r) * HD_ + c];
    }
    __syncthreads();

    float acc[4][4] = {};
    #pragma unroll
    for (int kk = 0; kk < 64; kk++) {
        float a[4], w[4];
        #pragma unroll
        for (int i = 0; i < 4; i++) a[i] = Qs[ty * 4 + i][kk];
        #pragma unroll
        for (int j = 0; j < 4; j++) w[j] = Ks[tx * 4 + j][kk];
        #pragma unroll
        for (int i = 0; i < 4; i++)
            #pragma unroll
            for (int j = 0; j < 4; j++)
                acc[i][j] = fmaf(a[i], w[j], acc[i][j]);
    }

    const int* mb = mask + (size_t)b * S_ * S_;
    float* ab = attn + (size_t)bh * S_ * S_;
    #pragma unroll
    for (int i = 0; i < 4; i++) {
        int q = bq + ty * 4 + i;
        #pragma unroll
        for (int j = 0; j < 4; j++) {
            int k = bk + tx * 4 + j;
            float e = acc[i][j] * SCALE_INV;
            if (mb[(size_t)q * S_ + k] == 0) e = NEGBIG;
            ab[(size_t)q * S_ + k] = e;
        }
    }
}

// ---------------------------------------------------------------------------
// Softmax over last dim (S_) in place; one block per row.
// ---------------------------------------------------------------------------
__global__ void softmax_kernel(float* __restrict__ attn) {
    __shared__ float sp[S_];
    __shared__ float red[256];
    const size_t row = blockIdx.x;
    float* p = attn + row * S_;
    const int tid = threadIdx.x;

    float mx = -INFINITY;
    #pragma unroll
    for (int k = tid; k < S_; k += 256) {
        float v = p[k];
        sp[k] = v;
        mx = fmaxf(mx, v);
    }
    red[tid] = mx;
    __syncthreads();
    #pragma unroll
    for (int s = 128; s > 0; s >>= 1) {
        if (tid < s) red[tid] = fmaxf(red[tid], red[tid + s]);
        __syncthreads();
    }
    mx = red[0];
    __syncthreads();

    float sum = 0.f;
    #pragma unroll
    for (int k = tid; k < S_; k += 256) {
        float e = __expf(sp[k] - mx);
        sp[k] = e;
        sum += e;
    }
    red[tid] = sum;
    __syncthreads();
    #pragma unroll
    for (int s = 128; s > 0; s >>= 1) {
        if (tid < s) red[tid] += red[tid + s];
        __syncthreads();
    }
    float inv = 1.0f / red[0];
    #pragma unroll
    for (int k = tid; k < S_; k += 256) p[k] = sp[k] * inv;
}

// ---------------------------------------------------------------------------
// PV: per (b,h): X[q,d] = sum_k P[q,k] * V[k,d]; write heads-merged [B,S,H]
// ---------------------------------------------------------------------------
__global__ void pv_kernel(const float* __restrict__ attn) {
    __shared__ float Ps[64][33];
    __shared__ float Vs[32][65];
    const int bh = blockIdx.z;
    const int b = bh / NH_, h = bh % NH_;
    const int bm = blockIdx.y * 64;
    const int tx = threadIdx.x, ty = threadIdx.y;
    const int tid = ty * 16 + tx;

    const float* Pb = attn + (size_t)bh * S_ * S_;
    const float* Vb = g_V + (size_t)bh * S_ * HD_;

    float acc[4][4] = {};
    for (int k0 = 0; k0 < S_; k0 += 32) {
        #pragma unroll
        for (int i = tid; i < 64 * 32; i += 256) {
            int r = i >> 5, c = i & 31;
            Ps[r][c] = Pb[(size_t)(bm + r) * S_ + k0 + c];
        }
        #pragma unroll
        for (int i = tid; i < 32 * 64; i += 256) {
            int r = i >> 6, c = i & 63;
            Vs[r][c] = Vb[(size_t)(k0 + r) * HD_ + c];
        }
        __syncthreads();
        #pragma unroll
        for (int kk = 0; kk < 32; kk++) {
            float a[4], v[4];
            #pragma unroll
            for (int i = 0; i < 4; i++) a[i] = Ps[ty * 4 + i][kk];
            #pragma unroll
            for (int j = 0; j < 4; j++) v[j] = Vs[kk][tx * 4 + j];
            #pragma unroll
            for (int i = 0; i < 4; i++)
                #pragma unroll
                for (int j = 0; j < 4; j++)
                    acc[i][j] = fmaf(a[i], v[j], acc[i][j]);
        }
        __syncthreads();
    }

    #pragma unroll
    for (int i = 0; i < 4; i++) {
        int s = bm + ty * 4 + i;
        #pragma unroll
        for (int j = 0; j < 4; j++) {
            int d = tx * 4 + j;
            g_X[((size_t)(b * S_ + s)) * H_ + h * HD_ + d] = acc[i][j];
        }
    }
}

// ---------------------------------------------------------------------------
extern "C" void kernel_launch(void* const* d_in, const int* in_sizes, int n_in,
                              void* d_out, int out_size) {
    const float* query = (const float*)d_in[0];
    const float* key   = (const float*)d_in[1];
    const float* value = (const float*)d_in[2];
    const int*   mask  = (const int*)d_in[3];
    const float* Wq = (const float*)d_in[4];  const float* bq = (const float*)d_in[5];
    const float* Wk = (const float*)d_in[6];  const float* bk = (const float*)d_in[7];
    const float* Wv = (const float*)d_in[8];  const float* bv = (const float*)d_in[9];
    const float* Wo = (const float*)d_in[10]; const float* bo = (const float*)d_in[11];

    float* out  = (float*)d_out;                       // outputs [B,S,H]
    float* attn = out + (size_t)B_ * S_ * H_;          // attention [B,NH,S,S]

    float *gQ, *gK, *gV, *gX;
    cudaGetSymbolAddress((void**)&gQ, g_Q);
    cudaGetSymbolAddress((void**)&gK, g_K);
    cudaGetSymbolAddress((void**)&gV, g_V);
    cudaGetSymbolAddress((void**)&gX, g_X);

    dim3 blk(16, 16);
    dim3 grid_proj(H_ / 64, M_ / 64);                  // (16, 128)

    gemm_proj<<<grid_proj, blk>>>(query, Wq, bq, gQ, 1);
    gemm_proj<<<grid_proj, blk>>>(key,   Wk, bk, gK, 1);
    gemm_proj<<<grid_proj, blk>>>(value, Wv, bv, gV, 1);

    dim3 grid_e(S_ / 64, S_ / 64, B_ * NH_);           // (32, 32, 64)
    energy_kernel<<<grid_e, blk>>>(mask, attn);

    softmax_kernel<<<B_ * NH_ * S_, 256>>>(attn);      // 131072 rows

    dim3 grid_pv(1, S_ / 64, B_ * NH_);                // (1, 32, 64)
    pv_kernel<<<grid_pv, blk>>>(attn);

    gemm_proj<<<grid_proj, blk>>>(gX, Wo, bo, out, 0);
}

// round 3
// speedup vs baseline: 3.7874x; 3.7874x over previous
#include <cuda_runtime.h>
#include <math.h>
#include <stdint.h>

#define B_  4
#define S_  2048
#define H_  1024
#define NH_ 16
#define HD_ 64
#define M_  (B_ * S_)
#define SCALE_INV 0.125f
#define NEGBIG   -1e10f

// Scratch (device globals — no allocation allowed)
__device__ float g_Q[M_ * H_];    // [B,NH,S,HD]
__device__ float g_K[M_ * H_];    // [B,NH,S,HD]
__device__ float g_V[M_ * H_];    // [B,NH,S,HD]
__device__ float g_X[M_ * H_];    // [B,S,H]

// ---------------------------------------------------------------------------
__device__ __forceinline__ uint32_t f2tf32(float x) {  // round-to-nearest tf32
    uint32_t r; asm("cvt.rna.tf32.f32 %0, %1;" : "=r"(r) : "f"(x)); return r;
}
__device__ __forceinline__ float tf32f(float x) { return __uint_as_float(f2tf32(x)); }

__device__ __forceinline__ void mma_tf32(float* c, const uint32_t* a, const uint32_t* b) {
    asm volatile("mma.sync.aligned.m16n8k8.row.col.f32.tf32.tf32.f32 "
        "{%0,%1,%2,%3}, {%4,%5,%6,%7}, {%8,%9}, {%0,%1,%2,%3};"
        : "+f"(c[0]), "+f"(c[1]), "+f"(c[2]), "+f"(c[3])
        : "r"(a[0]), "r"(a[1]), "r"(a[2]), "r"(a[3]), "r"(b[0]), "r"(b[1]));
}

// A fragment: 16x8 (m x k). a0=(r,c) a1=(r+8,c) a2=(r,c+4) a3=(r+8,c+4); r=lane>>2, c=lane&3
__device__ __forceinline__ void lda_frag(uint32_t* a, const float* s, int lds,
                                         int mbase, int k, int lane) {
    const float* p = s + (size_t)(mbase + (lane >> 2)) * lds + k + (lane & 3);
    a[0] = __float_as_uint(p[0]);
    a[1] = __float_as_uint(p[8 * lds]);
    a[2] = __float_as_uint(p[4]);
    a[3] = __float_as_uint(p[8 * lds + 4]);
}
// B fragment: 8x8 (k x n), col-major n: b0=(k=lane&3, n=lane>>2), b1=(k+4, n)
// SMEM stores B as [n][k] rows (n-major), so both come from one row.
__device__ __forceinline__ void ldb_frag(uint32_t* b, const float* s, int lds,
                                         int nbase, int k, int lane) {
    const float* p = s + (size_t)(nbase + (lane >> 2)) * lds + k + (lane & 3);
    b[0] = __float_as_uint(p[0]);
    b[1] = __float_as_uint(p[4]);
}

// ---------------------------------------------------------------------------
// Projection GEMM: C[m,n] = A[m,:]·W[n,:] + bias[n]
// CTA tile 128x128, K=1024 chunked by 32. 8 warps = 2(m) x 4(n), warp 64x32.
// mode 0: out[m][n]; mode 1: out[b,h,s,d]
// ---------------------------------------------------------------------------
__global__ __launch_bounds__(256) void proj_mma(const float* __restrict__ A,
                                                const float* __restrict__ W,
                                                const float* __restrict__ bias,
                                                float* __restrict__ out, int mode) {
    __shared__ float sA[128][36];
    __shared__ float sB[128][36];
    const int tid = threadIdx.x, lane = tid & 31, w = tid >> 5;
    const int wm = (w >> 2) * 64, wn = (w & 3) * 32;
    const int m0 = blockIdx.y * 128, n0 = blockIdx.x * 128;

    float acc[4][4][4] = {};

    for (int kc = 0; kc < H_; kc += 32) {
        #pragma unroll
        for (int i = tid; i < 1024; i += 256) {
            int r = i >> 3, c = (i & 7) * 4;
            float4 va = *(const float4*)&A[(size_t)(m0 + r) * H_ + kc + c];
            float4 vb = *(const float4*)&W[(size_t)(n0 + r) * H_ + kc + c];
            float4 ta = { tf32f(va.x), tf32f(va.y), tf32f(va.z), tf32f(va.w) };
            float4 tb = { tf32f(vb.x), tf32f(vb.y), tf32f(vb.z), tf32f(vb.w) };
            *(float4*)&sA[r][c] = ta;
            *(float4*)&sB[r][c] = tb;
        }
        __syncthreads();
        #pragma unroll
        for (int ks = 0; ks < 4; ks++) {
            uint32_t af[4][4], bf[4][2];
            #pragma unroll
            for (int mt = 0; mt < 4; mt++) lda_frag(af[mt], &sA[0][0], 36, wm + mt * 16, ks * 8, lane);
            #pragma unroll
            for (int nt = 0; nt < 4; nt++) ldb_frag(bf[nt], &sB[0][0], 36, wn + nt * 8, ks * 8, lane);
            #pragma unroll
            for (int mt = 0; mt < 4; mt++)
                #pragma unroll
                for (int nt = 0; nt < 4; nt++)
                    mma_tf32(acc[mt][nt], af[mt], bf[nt]);
        }
        __syncthreads();
    }

    #pragma unroll
    for (int mt = 0; mt < 4; mt++) {
        #pragma unroll
        for (int nt = 0; nt < 4; nt++) {
            int r0 = m0 + wm + mt * 16 + (lane >> 2);
            int c0 = n0 + wn + nt * 8 + (lane & 3) * 2;
            #pragma unroll
            for (int e = 0; e < 4; e++) {
                int m = r0 + (e >> 1) * 8;
                int n = c0 + (e & 1);
                float v = acc[mt][nt][e] + bias[n];
                if (mode == 0) {
                    out[(size_t)m * H_ + n] = v;
                } else {
                    int b = m >> 11, s = m & 2047, h = n >> 6, dd = n & 63;
                    out[(((size_t)(b * NH_ + h) * S_) + s) * HD_ + dd] = v;
                }
            }
        }
    }
}

// ---------------------------------------------------------------------------
// Energy: E[q,k] = (Q[q,:]·K[k,:]) * 1/8, masked. CTA tile 128(q) x 128(k), K=64.
// ---------------------------------------------------------------------------
__global__ __launch_bounds__(256) void energy_mma(const int* __restrict__ mask,
                                                  float* __restrict__ attn) {
    __shared__ float sA[128][36];
    __shared__ float sB[128][36];
    const int tid = threadIdx.x, lane = tid & 31, w = tid >> 5;
    const int wm = (w >> 2) * 64, wn = (w & 3) * 32;
    const int bh = blockIdx.z, b = bh >> 4;
    const int q0 = blockIdx.y * 128, k0 = blockIdx.x * 128;
    const float* Qb = g_Q + (size_t)bh * S_ * HD_;
    const float* Kb = g_K + (size_t)bh * S_ * HD_;

    float acc[4][4][4] = {};

    for (int kc = 0; kc < HD_; kc += 32) {
        #pragma unroll
        for (int i = tid; i < 1024; i += 256) {
            int r = i >> 3, c = (i & 7) * 4;
            float4 va = *(const float4*)&Qb[(size_t)(q0 + r) * HD_ + kc + c];
            float4 vb = *(const float4*)&Kb[(size_t)(k0 + r) * HD_ + kc + c];
            float4 ta = { tf32f(va.x), tf32f(va.y), tf32f(va.z), tf32f(va.w) };
            float4 tb = { tf32f(vb.x), tf32f(vb.y), tf32f(vb.z), tf32f(vb.w) };
            *(float4*)&sA[r][c] = ta;
            *(float4*)&sB[r][c] = tb;
        }
        __syncthreads();
        #pragma unroll
        for (int ks = 0; ks < 4; ks++) {
            uint32_t af[4][4], bf[4][2];
            #pragma unroll
            for (int mt = 0; mt < 4; mt++) lda_frag(af[mt], &sA[0][0], 36, wm + mt * 16, ks * 8, lane);
            #pragma unroll
            for (int nt = 0; nt < 4; nt++) ldb_frag(bf[nt], &sB[0][0], 36, wn + nt * 8, ks * 8, lane);
            #pragma unroll
            for (int mt = 0; mt < 4; mt++)
                #pragma unroll
                for (int nt = 0; nt < 4; nt++)
                    mma_tf32(acc[mt][nt], af[mt], bf[nt]);
        }
        __syncthreads();
    }

    const int* mb = mask + (size_t)b * S_ * S_;
    float* ab = attn + (size_t)bh * S_ * S_;
    #pragma unroll
    for (int mt = 0; mt < 4; mt++) {
        #pragma unroll
        for (int nt = 0; nt < 4; nt++) {
            int r0 = q0 + wm + mt * 16 + (lane >> 2);
            int c0 = k0 + wn + nt * 8 + (lane & 3) * 2;
            #pragma unroll
            for (int e = 0; e < 4; e++) {
                int q = r0 + (e >> 1) * 8;
                int k = c0 + (e & 1);
                float v = acc[mt][nt][e] * SCALE_INV;
                if (mb[(size_t)q * S_ + k] == 0) v = NEGBIG;
                ab[(size_t)q * S_ + k] = v;
            }
        }
    }
}

// ---------------------------------------------------------------------------
// Softmax over last dim (S_) in place; one block per row.
// ---------------------------------------------------------------------------
__global__ void softmax_kernel(float* __restrict__ attn) {
    __shared__ float sp[S_];
    __shared__ float red[256];
    float* p = attn + (size_t)blockIdx.x * S_;
    const int tid = threadIdx.x;

    float mx = -INFINITY;
    #pragma unroll
    for (int k = tid; k < S_; k += 256) { float v = p[k]; sp[k] = v; mx = fmaxf(mx, v); }
    red[tid] = mx; __syncthreads();
    #pragma unroll
    for (int s = 128; s > 0; s >>= 1) {
        if (tid < s) red[tid] = fmaxf(red[tid], red[tid + s]);
        __syncthreads();
    }
    mx = red[0]; __syncthreads();

    float sum = 0.f;
    #pragma unroll
    for (int k = tid; k < S_; k += 256) { float e = __expf(sp[k] - mx); sp[k] = e; sum += e; }
    red[tid] = sum; __syncthreads();
    #pragma unroll
    for (int s = 128; s > 0; s >>= 1) {
        if (tid < s) red[tid] += red[tid + s];
        __syncthreads();
    }
    float inv = 1.0f / red[0];
    #pragma unroll
    for (int k = tid; k < S_; k += 256) p[k] = sp[k] * inv;
}

// ---------------------------------------------------------------------------
// PV: X[q,d] = sum_k P[q,k]·V[k,d]. CTA tile 256(q) x 64(d), K=2048 chunked 32.
// 8 warps = 4(m) x 2(n), warp 64x32. B frag read from sV[k][d] (k-major rows).
// ---------------------------------------------------------------------------
__global__ __launch_bounds__(256) void pv_mma(const float* __restrict__ attn) {
    __shared__ float sP[256][36];
    __shared__ float sV[32][68];
    const int tid = threadIdx.x, lane = tid & 31, w = tid >> 5;
    const int wm = (w >> 1) * 64, wn = (w & 1) * 32;
    const int bh = blockIdx.y, b = bh >> 4, h = bh & 15;
    const int q0 = blockIdx.x * 256;
    const float* Pb = attn + (size_t)bh * S_ * S_;
    const float* Vb = g_V + (size_t)bh * S_ * HD_;

    float acc[4][4][4] = {};

    for (int kc = 0; kc < S_; kc += 32) {
        #pragma unroll
        for (int i = tid; i < 2048; i += 256) {
            int r = i >> 3, c = (i & 7) * 4;
            float4 va = *(const float4*)&Pb[(size_t)(q0 + r) * S_ + kc + c];
            float4 ta = { tf32f(va.x), tf32f(va.y), tf32f(va.z), tf32f(va.w) };
            *(float4*)&sP[r][c] = ta;
        }
        #pragma unroll
        for (int i = tid; i < 512; i += 256) {
            int r = i >> 4, c = (i & 15) * 4;
            float4 vb = *(const float4*)&Vb[(size_t)(kc + r) * HD_ + c];
            float4 tb = { tf32f(vb.x), tf32f(vb.y), tf32f(vb.z), tf32f(vb.w) };
            *(float4*)&sV[r][c] = tb;
        }
        __syncthreads();
        #pragma unroll
        for (int ks = 0; ks < 4; ks++) {
            uint32_t af[4][4], bf[4][2];
            #pragma unroll
            for (int mt = 0; mt < 4; mt++) lda_frag(af[mt], &sP[0][0], 36, wm + mt * 16, ks * 8, lane);
            // B frag from sV[k][d]: b0 = V[ks*8 + lane&3][nbase + lane>>2]
            #pragma unroll
            for (int nt = 0; nt < 4; nt++) {
                const float* p = &sV[ks * 8 + (lane & 3)][wn + nt * 8 + (lane >> 2)];
                bf[nt][0] = __float_as_uint(p[0]);
                bf[nt][1] = __float_as_uint(p[4 * 68]);
            }
            #pragma unroll
            for (int mt = 0; mt < 4; mt++)
                #pragma unroll
                for (int nt = 0; nt < 4; nt++)
                    mma_tf32(acc[mt][nt], af[mt], bf[nt]);
        }
        __syncthreads();
    }

    #pragma unroll
    for (int mt = 0; mt < 4; mt++) {
        #pragma unroll
        for (int nt = 0; nt < 4; nt++) {
            int r0 = q0 + wm + mt * 16 + (lane >> 2);
            int c0 = wn + nt * 8 + (lane & 3) * 2;
            #pragma unroll
            for (int e = 0; e < 4; e++) {
                int q = r0 + (e >> 1) * 8;
                int d = c0 + (e & 1);
                g_X[((size_t)(b * S_ + q)) * H_ + h * HD_ + d] = acc[mt][nt][e];
            }
        }
    }
}

// ---------------------------------------------------------------------------
extern "C" void kernel_launch(void* const* d_in, const int* in_sizes, int n_in,
                              void* d_out, int out_size) {
    const float* query = (const float*)d_in[0];
    const float* key   = (const float*)d_in[1];
    const float* value = (const float*)d_in[2];
    const int*   mask  = (const int*)d_in[3];
    const float* Wq = (const float*)d_in[4];  const float* bq = (const float*)d_in[5];
    const float* Wk = (const float*)d_in[6];  const float* bk = (const float*)d_in[7];
    const float* Wv = (const float*)d_in[8];  const float* bv = (const float*)d_in[9];
    const float* Wo = (const float*)d_in[10]; const float* bo = (const float*)d_in[11];

    float* out  = (float*)d_out;
    float* attn = out + (size_t)B_ * S_ * H_;

    float *gQ, *gK, *gV, *gX;
    cudaGetSymbolAddress((void**)&gQ, g_Q);
    cudaGetSymbolAddress((void**)&gK, g_K);
    cudaGetSymbolAddress((void**)&gV, g_V);
    cudaGetSymbolAddress((void**)&gX, g_X);

    dim3 grid_proj(H_ / 128, M_ / 128);        // (8, 64)
    proj_mma<<<grid_proj, 256>>>(query, Wq, bq, gQ, 1);
    proj_mma<<<grid_proj, 256>>>(key,   Wk, bk, gK, 1);
    proj_mma<<<grid_proj, 256>>>(value, Wv, bv, gV, 1);

    dim3 grid_e(S_ / 128, S_ / 128, B_ * NH_); // (16, 16, 64)
    energy_mma<<<grid_e, 256>>>(mask, attn);

    softmax_kernel<<<B_ * NH_ * S_, 256>>>(attn);

    dim3 grid_pv(S_ / 256, B_ * NH_);          // (8, 64)
    pv_mma<<<grid_pv, 256>>>(attn);

    proj_mma<<<grid_proj, 256>>>(gX, Wo, bo, out, 0);
}

// round 4
// speedup vs baseline: 4.2730x; 1.1282x over previous
#include <cuda_runtime.h>
#include <math.h>
#include <stdint.h>

#define B_  4
#define S_  2048
#define H_  1024
#define NH_ 16
#define HD_ 64
#define M_  (B_ * S_)
#define SCALE_INV 0.125f

// Scratch (device globals — no allocation allowed)
__device__ float g_Q[M_ * H_];            // [B,NH,S,HD]
__device__ float g_K[M_ * H_];            // [B,NH,S,HD]
__device__ float g_V[M_ * H_];            // [B,NH,S,HD]
__device__ float g_X[M_ * H_];            // [B,S,H]
__device__ float g_psum[64 * S_ * 16];    // [bh][q][kblock] partial row sums

// ---------------------------------------------------------------------------
__device__ __forceinline__ uint32_t f2tf32(float x) {  // round-to-nearest tf32
    uint32_t r; asm("cvt.rna.tf32.f32 %0, %1;" : "=r"(r) : "f"(x)); return r;
}
__device__ __forceinline__ float tf32f(float x) { return __uint_as_float(f2tf32(x)); }

__device__ __forceinline__ void mma_tf32(float* c, const uint32_t* a, const uint32_t* b) {
    asm volatile("mma.sync.aligned.m16n8k8.row.col.f32.tf32.tf32.f32 "
        "{%0,%1,%2,%3}, {%4,%5,%6,%7}, {%8,%9}, {%0,%1,%2,%3};"
        : "+f"(c[0]), "+f"(c[1]), "+f"(c[2]), "+f"(c[3])
        : "r"(a[0]), "r"(a[1]), "r"(a[2]), "r"(a[3]), "r"(b[0]), "r"(b[1]));
}

__device__ __forceinline__ void lda_frag(uint32_t* a, const float* s, int lds,
                                         int mbase, int k, int lane) {
    const float* p = s + (size_t)(mbase + (lane >> 2)) * lds + k + (lane & 3);
    a[0] = __float_as_uint(p[0]);
    a[1] = __float_as_uint(p[8 * lds]);
    a[2] = __float_as_uint(p[4]);
    a[3] = __float_as_uint(p[8 * lds + 4]);
}
__device__ __forceinline__ void ldb_frag(uint32_t* b, const float* s, int lds,
                                         int nbase, int k, int lane) {
    const float* p = s + (size_t)(nbase + (lane >> 2)) * lds + k + (lane & 3);
    b[0] = __float_as_uint(p[0]);
    b[1] = __float_as_uint(p[4]);
}

// ---------------------------------------------------------------------------
// Projection GEMM: C[m,n] = A[m,:]·W[n,:] + bias[n]. Tile 128x128.
// mode 0: out[m][n]; mode 1: out[b,h,s,d]
// ---------------------------------------------------------------------------
__global__ __launch_bounds__(256) void proj_mma(const float* __restrict__ A,
                                                const float* __restrict__ W,
                                                const float* __restrict__ bias,
                                                float* __restrict__ out, int mode) {
    __shared__ float sA[128][36];
    __shared__ float sB[128][36];
    const int tid = threadIdx.x, lane = tid & 31, w = tid >> 5;
    const int wm = (w >> 2) * 64, wn = (w & 3) * 32;
    const int m0 = blockIdx.y * 128, n0 = blockIdx.x * 128;

    float acc[4][4][4] = {};

    for (int kc = 0; kc < H_; kc += 32) {
        #pragma unroll
        for (int i = tid; i < 1024; i += 256) {
            int r = i >> 3, c = (i & 7) * 4;
            float4 va = *(const float4*)&A[(size_t)(m0 + r) * H_ + kc + c];
            float4 vb = *(const float4*)&W[(size_t)(n0 + r) * H_ + kc + c];
            float4 ta = { tf32f(va.x), tf32f(va.y), tf32f(va.z), tf32f(va.w) };
            float4 tb = { tf32f(vb.x), tf32f(vb.y), tf32f(vb.z), tf32f(vb.w) };
            *(float4*)&sA[r][c] = ta;
            *(float4*)&sB[r][c] = tb;
        }
        __syncthreads();
        #pragma unroll
        for (int ks = 0; ks < 4; ks++) {
            uint32_t af[4][4], bf[4][2];
            #pragma unroll
            for (int mt = 0; mt < 4; mt++) lda_frag(af[mt], &sA[0][0], 36, wm + mt * 16, ks * 8, lane);
            #pragma unroll
            for (int nt = 0; nt < 4; nt++) ldb_frag(bf[nt], &sB[0][0], 36, wn + nt * 8, ks * 8, lane);
            #pragma unroll
            for (int mt = 0; mt < 4; mt++)
                #pragma unroll
                for (int nt = 0; nt < 4; nt++)
                    mma_tf32(acc[mt][nt], af[mt], bf[nt]);
        }
        __syncthreads();
    }

    #pragma unroll
    for (int mt = 0; mt < 4; mt++) {
        #pragma unroll
        for (int nt = 0; nt < 4; nt++) {
            int r0 = m0 + wm + mt * 16 + (lane >> 2);
            int c0 = n0 + wn + nt * 8 + (lane & 3) * 2;
            #pragma unroll
            for (int e = 0; e < 4; e++) {
                int m = r0 + (e >> 1) * 8;
                int n = c0 + (e & 1);
                float v = acc[mt][nt][e] + bias[n];
                if (mode == 0) {
                    out[(size_t)m * H_ + n] = v;
                } else {
                    int b = m >> 11, s = m & 2047, h = n >> 6, dd = n & 63;
                    out[(((size_t)(b * NH_ + h) * S_) + s) * HD_ + dd] = v;
                }
            }
        }
    }
}

// ---------------------------------------------------------------------------
// Energy + exp + mask, coalesced epilogue. Tile 128(q) x 128(k).
// Writes unnormalized P = exp(E/8)*mask to attn, partial row sums to psum.
// ---------------------------------------------------------------------------
__global__ __launch_bounds__(256) void energy_exp(const int* __restrict__ mask,
                                                  float* __restrict__ attn,
                                                  float* __restrict__ psum) {
    __shared__ union {
        struct { float A[128][36]; float B[128][36]; } ld;
        float E[128][68];
    } sm;
    const int tid = threadIdx.x, lane = tid & 31, w = tid >> 5;
    const int wm = (w >> 2) * 64, wn = (w & 3) * 32;
    const int bh = blockIdx.z, b = bh >> 4;
    const int q0 = blockIdx.y * 128, k0 = blockIdx.x * 128;
    const int kblk = blockIdx.x;
    const float* Qb = g_Q + (size_t)bh * S_ * HD_;
    const float* Kb = g_K + (size_t)bh * S_ * HD_;

    float acc[4][4][4] = {};

    for (int kc = 0; kc < HD_; kc += 32) {
        #pragma unroll
        for (int i = tid; i < 1024; i += 256) {
            int r = i >> 3, c = (i & 7) * 4;
            float4 va = *(const float4*)&Qb[(size_t)(q0 + r) * HD_ + kc + c];
            float4 vb = *(const float4*)&Kb[(size_t)(k0 + r) * HD_ + kc + c];
            float4 ta = { tf32f(va.x), tf32f(va.y), tf32f(va.z), tf32f(va.w) };
            float4 tb = { tf32f(vb.x), tf32f(vb.y), tf32f(vb.z), tf32f(vb.w) };
            *(float4*)&sm.ld.A[r][c] = ta;
            *(float4*)&sm.ld.B[r][c] = tb;
        }
        __syncthreads();
        #pragma unroll
        for (int ks = 0; ks < 4; ks++) {
            uint32_t af[4][4], bf[4][2];
            #pragma unroll
            for (int mt = 0; mt < 4; mt++) lda_frag(af[mt], &sm.ld.A[0][0], 36, wm + mt * 16, ks * 8, lane);
            #pragma unroll
            for (int nt = 0; nt < 4; nt++) ldb_frag(bf[nt], &sm.ld.B[0][0], 36, wn + nt * 8, ks * 8, lane);
            #pragma unroll
            for (int mt = 0; mt < 4; mt++)
                #pragma unroll
                for (int nt = 0; nt < 4; nt++)
                    mma_tf32(acc[mt][nt], af[mt], bf[nt]);
        }
        __syncthreads();
    }

    // Coalesced epilogue: 2 passes over 64-column halves via SMEM staging.
    const int* mb = mask + (size_t)b * S_ * S_;
    float* ab = attn + (size_t)bh * S_ * S_;
    float rsum[8];
    #pragma unroll
    for (int j = 0; j < 8; j++) rsum[j] = 0.f;

    #pragma unroll
    for (int pass = 0; pass < 2; pass++) {
        __syncthreads();
        if (((w & 3) >> 1) == pass) {
            const int lc0 = (w & 1) * 32;
            #pragma unroll
            for (int mt = 0; mt < 4; mt++) {
                int r = wm + mt * 16 + (lane >> 2);
                #pragma unroll
                for (int nt = 0; nt < 4; nt++) {
                    int lc = lc0 + nt * 8 + (lane & 3) * 2;
                    sm.E[r][lc]         = acc[mt][nt][0];
                    sm.E[r][lc + 1]     = acc[mt][nt][1];
                    sm.E[r + 8][lc]     = acc[mt][nt][2];
                    sm.E[r + 8][lc + 1] = acc[mt][nt][3];
                }
            }
        }
        __syncthreads();
        #pragma unroll
        for (int j = 0; j < 8; j++) {
            int row = j * 16 + (tid >> 4);
            int q = q0 + row;
            int cl = (tid & 15) * 4;
            int k = k0 + pass * 64 + cl;
            float4 ev = *(float4*)&sm.E[row][cl];
            int4  mv = *(const int4*)&mb[(size_t)q * S_ + k];
            float p0 = mv.x ? __expf(ev.x * SCALE_INV) : 0.f;
            float p1 = mv.y ? __expf(ev.y * SCALE_INV) : 0.f;
            float p2 = mv.z ? __expf(ev.z * SCALE_INV) : 0.f;
            float p3 = mv.w ? __expf(ev.w * SCALE_INV) : 0.f;
            float4 pv4 = { p0, p1, p2, p3 };
            *(float4*)&ab[(size_t)q * S_ + k] = pv4;
            rsum[j] += (p0 + p1) + (p2 + p3);
        }
    }

    // Reduce row sums across the 16 threads sharing a row; write partials.
    #pragma unroll
    for (int j = 0; j < 8; j++) {
        float v = rsum[j];
        v += __shfl_xor_sync(0xffffffffu, v, 1);
        v += __shfl_xor_sync(0xffffffffu, v, 2);
        v += __shfl_xor_sync(0xffffffffu, v, 4);
        v += __shfl_xor_sync(0xffffffffu, v, 8);
        if ((tid & 15) == 0) {
            int row = j * 16 + (tid >> 4);
            psum[((size_t)bh * S_ + q0 + row) * 16 + kblk] = v;
        }
    }
}

// ---------------------------------------------------------------------------
// PV + normalize: X[q,d] = sum_k Pn[q,k]·V[k,d]; also writes Pn back to attn.
// Tile 256(q) x 64(d), K=2048 chunked by 32.
// ---------------------------------------------------------------------------
__global__ __launch_bounds__(256) void pv_norm(float* __restrict__ attn,
                                               const float* __restrict__ psum) {
    __shared__ float sP[256][36];
    __shared__ float sV[32][68];
    __shared__ float sInv[256];
    const int tid = threadIdx.x, lane = tid & 31, w = tid >> 5;
    const int wm = (w >> 1) * 64, wn = (w & 1) * 32;
    const int bh = blockIdx.y, b = bh >> 4, h = bh & 15;
    const int q0 = blockIdx.x * 256;
    float* Pb = attn + (size_t)bh * S_ * S_;
    const float* Vb = g_V + (size_t)bh * S_ * HD_;

    // Row sums -> reciprocals
    {
        const float* ps = psum + ((size_t)bh * S_ + q0 + tid) * 16;
        float s = 0.f;
        #pragma unroll
        for (int i = 0; i < 16; i++) s += ps[i];
        sInv[tid] = 1.0f / s;
    }
    __syncthreads();

    float acc[4][4][4] = {};

    for (int kc = 0; kc < S_; kc += 32) {
        #pragma unroll
        for (int i = tid; i < 2048; i += 256) {
            int r = i >> 3, c = (i & 7) * 4;
            float inv = sInv[r];
            float* gp = &Pb[(size_t)(q0 + r) * S_ + kc + c];
            float4 va = *(const float4*)gp;
            va.x *= inv; va.y *= inv; va.z *= inv; va.w *= inv;
            *(float4*)gp = va;   // normalized attention output
            float4 ta = { tf32f(va.x), tf32f(va.y), tf32f(va.z), tf32f(va.w) };
            *(float4*)&sP[r][c] = ta;
        }
        #pragma unroll
        for (int i = tid; i < 512; i += 256) {
            int r = i >> 4, c = (i & 15) * 4;
            float4 vb = *(const float4*)&Vb[(size_t)(kc + r) * HD_ + c];
            float4 tb = { tf32f(vb.x), tf32f(vb.y), tf32f(vb.z), tf32f(vb.w) };
            *(float4*)&sV[r][c] = tb;
        }
        __syncthreads();
        #pragma unroll
        for (int ks = 0; ks < 4; ks++) {
            uint32_t af[4][4], bf[4][2];
            #pragma unroll
            for (int mt = 0; mt < 4; mt++) lda_frag(af[mt], &sP[0][0], 36, wm + mt * 16, ks * 8, lane);
            #pragma unroll
            for (int nt = 0; nt < 4; nt++) {
                const float* p = &sV[ks * 8 + (lane & 3)][wn + nt * 8 + (lane >> 2)];
                bf[nt][0] = __float_as_uint(p[0]);
                bf[nt][1] = __float_as_uint(p[4 * 68]);
            }
            #pragma unroll
            for (int mt = 0; mt < 4; mt++)
                #pragma unroll
                for (int nt = 0; nt < 4; nt++)
                    mma_tf32(acc[mt][nt], af[mt], bf[nt]);
        }
        __syncthreads();
    }

    #pragma unroll
    for (int mt = 0; mt < 4; mt++) {
        #pragma unroll
        for (int nt = 0; nt < 4; nt++) {
            int r0 = q0 + wm + mt * 16 + (lane >> 2);
            int c0 = wn + nt * 8 + (lane & 3) * 2;
            #pragma unroll
            for (int e = 0; e < 4; e++) {
                int q = r0 + (e >> 1) * 8;
                int d = c0 + (e & 1);
                g_X[((size_t)(b * S_ + q)) * H_ + h * HD_ + d] = acc[mt][nt][e];
            }
        }
    }
}

// ---------------------------------------------------------------------------
extern "C" void kernel_launch(void* const* d_in, const int* in_sizes, int n_in,
                              void* d_out, int out_size) {
    const float* query = (const float*)d_in[0];
    const float* key   = (const float*)d_in[1];
    const float* value = (const float*)d_in[2];
    const int*   mask  = (const int*)d_in[3];
    const float* Wq = (const float*)d_in[4];  const float* bq = (const float*)d_in[5];
    const float* Wk = (const float*)d_in[6];  const float* bk = (const float*)d_in[7];
    const float* Wv = (const float*)d_in[8];  const float* bv = (const float*)d_in[9];
    const float* Wo = (const float*)d_in[10]; const float* bo = (const float*)d_in[11];

    float* out  = (float*)d_out;
    float* attn = out + (size_t)B_ * S_ * H_;

    float *gQ, *gK, *gV, *gX, *gPS;
    cudaGetSymbolAddress((void**)&gQ, g_Q);
    cudaGetSymbolAddress((void**)&gK, g_K);
    cudaGetSymbolAddress((void**)&gV, g_V);
    cudaGetSymbolAddress((void**)&gX, g_X);
    cudaGetSymbolAddress((void**)&gPS, g_psum);

    dim3 grid_proj(H_ / 128, M_ / 128);        // (8, 64)
    proj_mma<<<grid_proj, 256>>>(query, Wq, bq, gQ, 1);
    proj_mma<<<grid_proj, 256>>>(key,   Wk, bk, gK, 1);
    proj_mma<<<grid_proj, 256>>>(value, Wv, bv, gV, 1);

    dim3 grid_e(S_ / 128, S_ / 128, B_ * NH_); // (16, 16, 64)
    energy_exp<<<grid_e, 256>>>(mask, attn, gPS);

    dim3 grid_pv(S_ / 256, B_ * NH_);          // (8, 64)
    pv_norm<<<grid_pv, 256>>>(attn, gPS);

    proj_mma<<<grid_proj, 256>>>(gX, Wo, bo, out, 0);
}

// round 5
// speedup vs baseline: 5.2240x; 1.2226x over previous
#include <cuda_runtime.h>
#include <math.h>
#include <stdint.h>

#define B_  4
#define S_  2048
#define H_  1024
#define NH_ 16
#define HD_ 64
#define M_  (B_ * S_)
#define SCALE_INV 0.125f

// Scratch (device globals — no allocation allowed)
__device__ float g_Q[M_ * H_];            // [B,NH,S,HD]  tf32-rounded
__device__ float g_K[M_ * H_];            // [B,NH,S,HD]  tf32-rounded
__device__ float g_V[M_ * H_];            // [B,NH,S,HD]  tf32-rounded
__device__ float g_X[M_ * H_];            // [B,S,H]
__device__ float g_psum[64 * S_ * 16];    // [bh][q][kblock] partial row sums

// ---------------------------------------------------------------------------
__device__ __forceinline__ uint32_t f2tf32(float x) {  // round-to-nearest tf32
    uint32_t r; asm("cvt.rna.tf32.f32 %0, %1;" : "=r"(r) : "f"(x)); return r;
}
__device__ __forceinline__ float tf32f(float x) { return __uint_as_float(f2tf32(x)); }

__device__ __forceinline__ void mma_tf32(float* c, const uint32_t* a, const uint32_t* b) {
    asm volatile("mma.sync.aligned.m16n8k8.row.col.f32.tf32.tf32.f32 "
        "{%0,%1,%2,%3}, {%4,%5,%6,%7}, {%8,%9}, {%0,%1,%2,%3};"
        : "+f"(c[0]), "+f"(c[1]), "+f"(c[2]), "+f"(c[3])
        : "r"(a[0]), "r"(a[1]), "r"(a[2]), "r"(a[3]), "r"(b[0]), "r"(b[1]));
}

__device__ __forceinline__ void lda_frag(uint32_t* a, const float* s, int lds,
                                         int mbase, int k, int lane) {
    const float* p = s + (size_t)(mbase + (lane >> 2)) * lds + k + (lane & 3);
    a[0] = __float_as_uint(p[0]);
    a[1] = __float_as_uint(p[8 * lds]);
    a[2] = __float_as_uint(p[4]);
    a[3] = __float_as_uint(p[8 * lds + 4]);
}
__device__ __forceinline__ void ldb_frag(uint32_t* b, const float* s, int lds,
                                         int nbase, int k, int lane) {
    const float* p = s + (size_t)(nbase + (lane >> 2)) * lds + k + (lane & 3);
    b[0] = __float_as_uint(p[0]);
    b[1] = __float_as_uint(p[4]);
}

__device__ __forceinline__ uint32_t smaddr(const void* p) {
    return (uint32_t)__cvta_generic_to_shared(p);
}
#define CP_ASYNC16(dst, src) \
    asm volatile("cp.async.cg.shared.global [%0], [%1], 16;" :: "r"(dst), "l"(src))
#define CP_COMMIT() asm volatile("cp.async.commit_group;" ::: "memory")
#define CP_WAIT0()  asm volatile("cp.async.wait_group 0;" ::: "memory")
#define CP_WAIT1()  asm volatile("cp.async.wait_group 1;" ::: "memory")

// ---------------------------------------------------------------------------
// Projection GEMM: C[m,n] = A[m,:]·W[n,:] + bias[n]. Tile 128x128.
// mode 0: out[m][n] fp32; mode 1: out[b,h,s,d] tf32-rounded
// ---------------------------------------------------------------------------
__global__ __launch_bounds__(256) void proj_mma(const float* __restrict__ A,
                                                const float* __restrict__ W,
                                                const float* __restrict__ bias,
                                                float* __restrict__ out, int mode) {
    __shared__ float sA[128][36];
    __shared__ float sB[128][36];
    const int tid = threadIdx.x, lane = tid & 31, w = tid >> 5;
    const int wm = (w >> 2) * 64, wn = (w & 3) * 32;
    const int m0 = blockIdx.y * 128, n0 = blockIdx.x * 128;

    float acc[4][4][4] = {};

    for (int kc = 0; kc < H_; kc += 32) {
        #pragma unroll
        for (int i = tid; i < 1024; i += 256) {
            int r = i >> 3, c = (i & 7) * 4;
            float4 va = *(const float4*)&A[(size_t)(m0 + r) * H_ + kc + c];
            float4 vb = *(const float4*)&W[(size_t)(n0 + r) * H_ + kc + c];
            float4 ta = { tf32f(va.x), tf32f(va.y), tf32f(va.z), tf32f(va.w) };
            float4 tb = { tf32f(vb.x), tf32f(vb.y), tf32f(vb.z), tf32f(vb.w) };
            *(float4*)&sA[r][c] = ta;
            *(float4*)&sB[r][c] = tb;
        }
        __syncthreads();
        #pragma unroll
        for (int ks = 0; ks < 4; ks++) {
            uint32_t af[4][4], bf[4][2];
            #pragma unroll
            for (int mt = 0; mt < 4; mt++) lda_frag(af[mt], &sA[0][0], 36, wm + mt * 16, ks * 8, lane);
            #pragma unroll
            for (int nt = 0; nt < 4; nt++) ldb_frag(bf[nt], &sB[0][0], 36, wn + nt * 8, ks * 8, lane);
            #pragma unroll
            for (int mt = 0; mt < 4; mt++)
                #pragma unroll
                for (int nt = 0; nt < 4; nt++)
                    mma_tf32(acc[mt][nt], af[mt], bf[nt]);
        }
        __syncthreads();
    }

    #pragma unroll
    for (int mt = 0; mt < 4; mt++) {
        #pragma unroll
        for (int nt = 0; nt < 4; nt++) {
            int r0 = m0 + wm + mt * 16 + (lane >> 2);
            int c0 = n0 + wn + nt * 8 + (lane & 3) * 2;
            #pragma unroll
            for (int e = 0; e < 4; e++) {
                int m = r0 + (e >> 1) * 8;
                int n = c0 + (e & 1);
                float v = acc[mt][nt][e] + bias[n];
                if (mode == 0) {
                    out[(size_t)m * H_ + n] = v;
                } else {
                    int b = m >> 11, s = m & 2047, h = n >> 6, dd = n & 63;
                    out[(((size_t)(b * NH_ + h) * S_) + s) * HD_ + dd] = tf32f(v);
                }
            }
        }
    }
}

// ---------------------------------------------------------------------------
// Energy + exp + mask. Tile 128(q) x 128(k). Single-shot cp.async tile load
// (operands pre-rounded tf32). Writes tf32-rounded unnormalized P to attn,
// partial row sums to psum.
// ---------------------------------------------------------------------------
__global__ __launch_bounds__(256) void energy_exp(const int* __restrict__ mask,
                                                  float* __restrict__ attn,
                                                  float* __restrict__ psum) {
    __shared__ union {
        struct { float A[128][68]; float B[128][68]; } ld;
        float E[128][68];
    } sm;
    const int tid = threadIdx.x, lane = tid & 31, w = tid >> 5;
    const int wm = (w >> 2) * 64, wn = (w & 3) * 32;
    const int bh = blockIdx.z, b = bh >> 4;
    const int q0 = blockIdx.y * 128, k0 = blockIdx.x * 128;
    const int kblk = blockIdx.x;
    const float* Qb = g_Q + (size_t)bh * S_ * HD_;
    const float* Kb = g_K + (size_t)bh * S_ * HD_;

    // Single-shot load of Q[128][64] and K[128][64] tiles.
    #pragma unroll
    for (int i = tid; i < 2048; i += 256) {
        int r = i >> 4, c4 = (i & 15) * 4;
        CP_ASYNC16(smaddr(&sm.ld.A[r][c4]), &Qb[(size_t)(q0 + r) * HD_ + c4]);
        CP_ASYNC16(smaddr(&sm.ld.B[r][c4]), &Kb[(size_t)(k0 + r) * HD_ + c4]);
    }
    CP_COMMIT();
    CP_WAIT0();
    __syncthreads();

    float acc[4][4][4] = {};
    #pragma unroll
    for (int ks = 0; ks < 8; ks++) {
        uint32_t af[4][4], bf[4][2];
        #pragma unroll
        for (int mt = 0; mt < 4; mt++) lda_frag(af[mt], &sm.ld.A[0][0], 68, wm + mt * 16, ks * 8, lane);
        #pragma unroll
        for (int nt = 0; nt < 4; nt++) ldb_frag(bf[nt], &sm.ld.B[0][0], 68, wn + nt * 8, ks * 8, lane);
        #pragma unroll
        for (int mt = 0; mt < 4; mt++)
            #pragma unroll
            for (int nt = 0; nt < 4; nt++)
                mma_tf32(acc[mt][nt], af[mt], bf[nt]);
    }

    // Coalesced epilogue: 2 passes over 64-column halves via SMEM staging.
    const int* mb = mask + (size_t)b * S_ * S_;
    float* ab = attn + (size_t)bh * S_ * S_;
    float rsum[8];
    #pragma unroll
    for (int j = 0; j < 8; j++) rsum[j] = 0.f;

    #pragma unroll
    for (int pass = 0; pass < 2; pass++) {
        __syncthreads();
        if (((w & 3) >> 1) == pass) {
            const int lc0 = (w & 1) * 32;
            #pragma unroll
            for (int mt = 0; mt < 4; mt++) {
                int r = wm + mt * 16 + (lane >> 2);
                #pragma unroll
                for (int nt = 0; nt < 4; nt++) {
                    int lc = lc0 + nt * 8 + (lane & 3) * 2;
                    sm.E[r][lc]         = acc[mt][nt][0];
                    sm.E[r][lc + 1]     = acc[mt][nt][1];
                    sm.E[r + 8][lc]     = acc[mt][nt][2];
                    sm.E[r + 8][lc + 1] = acc[mt][nt][3];
                }
            }
        }
        __syncthreads();
        #pragma unroll
        for (int j = 0; j < 8; j++) {
            int row = j * 16 + (tid >> 4);
            int q = q0 + row;
            int cl = (tid & 15) * 4;
            int k = k0 + pass * 64 + cl;
            float4 ev = *(float4*)&sm.E[row][cl];
            int4  mv = *(const int4*)&mb[(size_t)q * S_ + k];
            float p0 = mv.x ? tf32f(__expf(ev.x * SCALE_INV)) : 0.f;
            float p1 = mv.y ? tf32f(__expf(ev.y * SCALE_INV)) : 0.f;
            float p2 = mv.z ? tf32f(__expf(ev.z * SCALE_INV)) : 0.f;
            float p3 = mv.w ? tf32f(__expf(ev.w * SCALE_INV)) : 0.f;
            float4 pv4 = { p0, p1, p2, p3 };
            *(float4*)&ab[(size_t)q * S_ + k] = pv4;
            rsum[j] += (p0 + p1) + (p2 + p3);
        }
    }

    #pragma unroll
    for (int j = 0; j < 8; j++) {
        float v = rsum[j];
        v += __shfl_xor_sync(0xffffffffu, v, 1);
        v += __shfl_xor_sync(0xffffffffu, v, 2);
        v += __shfl_xor_sync(0xffffffffu, v, 4);
        v += __shfl_xor_sync(0xffffffffu, v, 8);
        if ((tid & 15) == 0) {
            int row = j * 16 + (tid >> 4);
            psum[((size_t)bh * S_ + q0 + row) * 16 + kblk] = v;
        }
    }
}

// ---------------------------------------------------------------------------
// PV + normalize. Tile 256(q) x 64(d), K chunked by 32, double-buffered
// cp.async. MMA uses UNNORMALIZED P (already tf32); normalization applied at
// the attn chunk store and the X epilogue (linearity).
// ---------------------------------------------------------------------------
__global__ __launch_bounds__(256) void pv_norm(float* __restrict__ attn,
                                               const float* __restrict__ psum) {
    __shared__ float sP[2][256][36];
    __shared__ float sV[2][32][68];
    __shared__ float sInv[256];
    const int tid = threadIdx.x, lane = tid & 31, w = tid >> 5;
    const int wm = (w >> 1) * 64, wn = (w & 1) * 32;
    const int bh = blockIdx.y, b = bh >> 4, h = bh & 15;
    const int q0 = blockIdx.x * 256;
    float* Pb = attn + (size_t)bh * S_ * S_;
    const float* Vb = g_V + (size_t)bh * S_ * HD_;

    {
        const float* ps = psum + ((size_t)bh * S_ + q0 + tid) * 16;
        float s = 0.f;
        #pragma unroll
        for (int i = 0; i < 16; i++) s += ps[i];
        sInv[tid] = 1.0f / s;
    }

    // Prefetch stage 0
    {
        #pragma unroll
        for (int i = tid; i < 2048; i += 256) {
            int r = i >> 3, c4 = (i & 7) * 4;
            CP_ASYNC16(smaddr(&sP[0][r][c4]), &Pb[(size_t)(q0 + r) * S_ + c4]);
        }
        #pragma unroll
        for (int i = tid; i < 512; i += 256) {
            int r = i >> 4, c4 = (i & 15) * 4;
            CP_ASYNC16(smaddr(&sV[0][r][c4]), &Vb[(size_t)r * HD_ + c4]);
        }
        CP_COMMIT();
    }

    float acc[4][4][4] = {};

    for (int it = 0; it < 64; it++) {
        const int kc = it * 32, s = it & 1;
        if (it + 1 < 64) {
            const int kn = kc + 32, sn = s ^ 1;
            #pragma unroll
            for (int i = tid; i < 2048; i += 256) {
                int r = i >> 3, c4 = (i & 7) * 4;
                CP_ASYNC16(smaddr(&sP[sn][r][c4]), &Pb[(size_t)(q0 + r) * S_ + kn + c4]);
            }
            #pragma unroll
            for (int i = tid; i < 512; i += 256) {
                int r = i >> 4, c4 = (i & 15) * 4;
                CP_ASYNC16(smaddr(&sV[sn][r][c4]), &Vb[(size_t)(kn + r) * HD_ + c4]);
            }
            CP_COMMIT();
            CP_WAIT1();
        } else {
            CP_WAIT0();
        }
        __syncthreads();

        #pragma unroll
        for (int ks = 0; ks < 4; ks++) {
            uint32_t af[4][4], bf[4][2];
            #pragma unroll
            for (int mt = 0; mt < 4; mt++) lda_frag(af[mt], &sP[s][0][0], 36, wm + mt * 16, ks * 8, lane);
            #pragma unroll
            for (int nt = 0; nt < 4; nt++) {
                const float* p = &sV[s][ks * 8 + (lane & 3)][wn + nt * 8 + (lane >> 2)];
                bf[nt][0] = __float_as_uint(p[0]);
                bf[nt][1] = __float_as_uint(p[4 * 68]);
            }
            #pragma unroll
            for (int mt = 0; mt < 4; mt++)
                #pragma unroll
                for (int nt = 0; nt < 4; nt++)
                    mma_tf32(acc[mt][nt], af[mt], bf[nt]);
        }

        // Normalized attention store for this chunk (coalesced float4).
        #pragma unroll
        for (int i = tid; i < 2048; i += 256) {
            int r = i >> 3, c4 = (i & 7) * 4;
            float inv = sInv[r];
            float4 v = *(float4*)&sP[s][r][c4];
            v.x *= inv; v.y *= inv; v.z *= inv; v.w *= inv;
            *(float4*)&Pb[(size_t)(q0 + r) * S_ + kc + c4] = v;
        }
        __syncthreads();
    }

    #pragma unroll
    for (int mt = 0; mt < 4; mt++) {
        #pragma unroll
        for (int nt = 0; nt < 4; nt++) {
            int rr = wm + mt * 16 + (lane >> 2);
            int c0 = wn + nt * 8 + (lane & 3) * 2;
            #pragma unroll
            for (int e = 0; e < 4; e++) {
                int rl = rr + (e >> 1) * 8;
                int q = q0 + rl;
                int d = c0 + (e & 1);
                g_X[((size_t)(b * S_ + q)) * H_ + h * HD_ + d] = acc[mt][nt][e] * sInv[rl];
            }
        }
    }
}

// ---------------------------------------------------------------------------
extern "C" void kernel_launch(void* const* d_in, const int* in_sizes, int n_in,
                              void* d_out, int out_size) {
    const float* query = (const float*)d_in[0];
    const float* key   = (const float*)d_in[1];
    const float* value = (const float*)d_in[2];
    const int*   mask  = (const int*)d_in[3];
    const float* Wq = (const float*)d_in[4];  const float* bq = (const float*)d_in[5];
    const float* Wk = (const float*)d_in[6];  const float* bk = (const float*)d_in[7];
    const float* Wv = (const float*)d_in[8];  const float* bv = (const float*)d_in[9];
    const float* Wo = (const float*)d_in[10]; const float* bo = (const float*)d_in[11];

    float* out  = (float*)d_out;
    float* attn = out + (size_t)B_ * S_ * H_;

    float *gQ, *gK, *gV, *gX, *gPS;
    cudaGetSymbolAddress((void**)&gQ, g_Q);
    cudaGetSymbolAddress((void**)&gK, g_K);
    cudaGetSymbolAddress((void**)&gV, g_V);
    cudaGetSymbolAddress((void**)&gX, g_X);
    cudaGetSymbolAddress((void**)&gPS, g_psum);

    dim3 grid_proj(H_ / 128, M_ / 128);        // (8, 64)
    proj_mma<<<grid_proj, 256>>>(query, Wq, bq, gQ, 1);
    proj_mma<<<grid_proj, 256>>>(key,   Wk, bk, gK, 1);
    proj_mma<<<grid_proj, 256>>>(value, Wv, bv, gV, 1);

    dim3 grid_e(S_ / 128, S_ / 128, B_ * NH_); // (16, 16, 64)
    energy_exp<<<grid_e, 256>>>(mask, attn, gPS);

    dim3 grid_pv(S_ / 256, B_ * NH_);          // (8, 64)
    pv_norm<<<grid_pv, 256>>>(attn, gPS);

    proj_mma<<<grid_proj, 256>>>(gX, Wo, bo, out, 0);
}

// round 6
// speedup vs baseline: 5.5924x; 1.0705x over previous
#include <cuda_runtime.h>
#include <math.h>
#include <stdint.h>

#define B_  4
#define S_  2048
#define H_  1024
#define NH_ 16
#define HD_ 64
#define M_  (B_ * S_)
#define SCALE_INV 0.125f

// Scratch (device globals — no allocation allowed)
__device__ float g_Q[M_ * H_];            // [B,NH,S,HD]  tf32-rounded
__device__ float g_K[M_ * H_];            // [B,NH,S,HD]  tf32-rounded
__device__ float g_V[M_ * H_];            // [B,NH,S,HD]  tf32-rounded
__device__ float g_X[M_ * H_];            // [B,S,H]
__device__ float g_psum[64 * S_ * 32];    // [bh][q][kblock(64)] partial row sums

// ---------------------------------------------------------------------------
__device__ __forceinline__ uint32_t f2tf32(float x) {  // round-to-nearest tf32
    uint32_t r; asm("cvt.rna.tf32.f32 %0, %1;" : "=r"(r) : "f"(x)); return r;
}
__device__ __forceinline__ float tf32f(float x) { return __uint_as_float(f2tf32(x)); }

__device__ __forceinline__ void mma_tf32(float* c, const uint32_t* a, const uint32_t* b) {
    asm volatile("mma.sync.aligned.m16n8k8.row.col.f32.tf32.tf32.f32 "
        "{%0,%1,%2,%3}, {%4,%5,%6,%7}, {%8,%9}, {%0,%1,%2,%3};"
        : "+f"(c[0]), "+f"(c[1]), "+f"(c[2]), "+f"(c[3])
        : "r"(a[0]), "r"(a[1]), "r"(a[2]), "r"(a[3]), "r"(b[0]), "r"(b[1]));
}

__device__ __forceinline__ void lda_frag(uint32_t* a, const float* s, int lds,
                                         int mbase, int k, int lane) {
    const float* p = s + (size_t)(mbase + (lane >> 2)) * lds + k + (lane & 3);
    a[0] = __float_as_uint(p[0]);
    a[1] = __float_as_uint(p[8 * lds]);
    a[2] = __float_as_uint(p[4]);
    a[3] = __float_as_uint(p[8 * lds + 4]);
}
__device__ __forceinline__ void ldb_frag(uint32_t* b, const float* s, int lds,
                                         int nbase, int k, int lane) {
    const float* p = s + (size_t)(nbase + (lane >> 2)) * lds + k + (lane & 3);
    b[0] = __float_as_uint(p[0]);
    b[1] = __float_as_uint(p[4]);
}

__device__ __forceinline__ uint32_t smaddr(const void* p) {
    return (uint32_t)__cvta_generic_to_shared(p);
}
#define CP_ASYNC16(dst, src) \
    asm volatile("cp.async.cg.shared.global [%0], [%1], 16;" :: "r"(dst), "l"(src))
#define CP_COMMIT() asm volatile("cp.async.commit_group;" ::: "memory")
#define CP_WAIT0()  asm volatile("cp.async.wait_group 0;" ::: "memory")
#define CP_WAIT1()  asm volatile("cp.async.wait_group 1;" ::: "memory")

// ---------------------------------------------------------------------------
// Projection GEMM: C[m,n] = A[m,:]·W[n,:] + bias[n]. Tile 128x128, cp.async
// 2-stage, tf32 cvt applied on fragments (hidden under MMA).
// mode 0: out[m][n] fp32; mode 1: out[b,h,s,d] tf32-rounded
// ---------------------------------------------------------------------------
__global__ __launch_bounds__(256, 2) void proj_mma(const float* __restrict__ A,
                                                   const float* __restrict__ W,
                                                   const float* __restrict__ bias,
                                                   float* __restrict__ out, int mode) {
    __shared__ float sA[2][128][36];
    __shared__ float sB[2][128][36];
    const int tid = threadIdx.x, lane = tid & 31, w = tid >> 5;
    const int wm = (w >> 2) * 64, wn = (w & 3) * 32;
    const int m0 = blockIdx.y * 128, n0 = blockIdx.x * 128;

    float acc[4][4][4] = {};

    // Prefetch chunk 0
    #pragma unroll
    for (int i = tid; i < 1024; i += 256) {
        int r = i >> 3, c4 = (i & 7) * 4;
        CP_ASYNC16(smaddr(&sA[0][r][c4]), &A[(size_t)(m0 + r) * H_ + c4]);
        CP_ASYNC16(smaddr(&sB[0][r][c4]), &W[(size_t)(n0 + r) * H_ + c4]);
    }
    CP_COMMIT();

    for (int it = 0; it < 32; it++) {
        const int s = it & 1;
        if (it + 1 < 32) {
            const int kn = (it + 1) * 32, sn = s ^ 1;
            #pragma unroll
            for (int i = tid; i < 1024; i += 256) {
                int r = i >> 3, c4 = (i & 7) * 4;
                CP_ASYNC16(smaddr(&sA[sn][r][c4]), &A[(size_t)(m0 + r) * H_ + kn + c4]);
                CP_ASYNC16(smaddr(&sB[sn][r][c4]), &W[(size_t)(n0 + r) * H_ + kn + c4]);
            }
            CP_COMMIT();
            CP_WAIT1();
        } else {
            CP_WAIT0();
        }
        __syncthreads();

        #pragma unroll
        for (int ks = 0; ks < 4; ks++) {
            uint32_t af[4][4], bf[4][2];
            #pragma unroll
            for (int mt = 0; mt < 4; mt++) {
                lda_frag(af[mt], &sA[s][0][0], 36, wm + mt * 16, ks * 8, lane);
                #pragma unroll
                for (int j = 0; j < 4; j++) af[mt][j] = f2tf32(__uint_as_float(af[mt][j]));
            }
            #pragma unroll
            for (int nt = 0; nt < 4; nt++) {
                ldb_frag(bf[nt], &sB[s][0][0], 36, wn + nt * 8, ks * 8, lane);
                bf[nt][0] = f2tf32(__uint_as_float(bf[nt][0]));
                bf[nt][1] = f2tf32(__uint_as_float(bf[nt][1]));
            }
            #pragma unroll
            for (int mt = 0; mt < 4; mt++)
                #pragma unroll
                for (int nt = 0; nt < 4; nt++)
                    mma_tf32(acc[mt][nt], af[mt], bf[nt]);
        }
        __syncthreads();
    }

    #pragma unroll
    for (int mt = 0; mt < 4; mt++) {
        #pragma unroll
        for (int nt = 0; nt < 4; nt++) {
            int r0 = m0 + wm + mt * 16 + (lane >> 2);
            int c0 = n0 + wn + nt * 8 + (lane & 3) * 2;
            #pragma unroll
            for (int e = 0; e < 4; e++) {
                int m = r0 + (e >> 1) * 8;
                int n = c0 + (e & 1);
                float v = acc[mt][nt][e] + bias[n];
                if (mode == 0) {
                    out[(size_t)m * H_ + n] = v;
                } else {
                    int b = m >> 11, sq = m & 2047, h = n >> 6, dd = n & 63;
                    out[(((size_t)(b * NH_ + h) * S_) + sq) * HD_ + dd] = tf32f(v);
                }
            }
        }
    }
}

// ---------------------------------------------------------------------------
// Energy + exp + mask. Tile 128(q) x 64(k), warp tile 32x32, single k=64 dot
// pass. Q/K pre-rounded tf32 -> no cvt. Writes tf32-rounded unnormalized P.
// ---------------------------------------------------------------------------
__global__ __launch_bounds__(256, 3) void energy_exp(const int* __restrict__ mask,
                                                     float* __restrict__ attn,
                                                     float* __restrict__ psum) {
    __shared__ union {
        struct { float A[128][68]; float B[64][68]; } ld;
        float E[128][68];
    } sm;
    const int tid = threadIdx.x, lane = tid & 31, w = tid >> 5;
    const int wm = (w >> 1) * 32, wn = (w & 1) * 32;
    const int bh = blockIdx.z, b = bh >> 4;
    const int q0 = blockIdx.y * 128, k0 = blockIdx.x * 64;
    const int kblk = blockIdx.x;
    const float* Qb = g_Q + (size_t)bh * S_ * HD_;
    const float* Kb = g_K + (size_t)bh * S_ * HD_;

    // One-shot load: Q[128][64], K[64][64]
    #pragma unroll
    for (int i = tid; i < 2048; i += 256) {
        int r = i >> 4, c4 = (i & 15) * 4;
        CP_ASYNC16(smaddr(&sm.ld.A[r][c4]), &Qb[(size_t)(q0 + r) * HD_ + c4]);
    }
    #pragma unroll
    for (int i = tid; i < 1024; i += 256) {
        int r = i >> 4, c4 = (i & 15) * 4;
        CP_ASYNC16(smaddr(&sm.ld.B[r][c4]), &Kb[(size_t)(k0 + r) * HD_ + c4]);
    }
    CP_COMMIT();
    CP_WAIT0();
    __syncthreads();

    float acc[2][4][4] = {};
    #pragma unroll
    for (int ks = 0; ks < 8; ks++) {
        uint32_t af[2][4], bf[4][2];
        #pragma unroll
        for (int mt = 0; mt < 2; mt++) lda_frag(af[mt], &sm.ld.A[0][0], 68, wm + mt * 16, ks * 8, lane);
        #pragma unroll
        for (int nt = 0; nt < 4; nt++) ldb_frag(bf[nt], &sm.ld.B[0][0], 68, wn + nt * 8, ks * 8, lane);
        #pragma unroll
        for (int mt = 0; mt < 2; mt++)
            #pragma unroll
            for (int nt = 0; nt < 4; nt++)
                mma_tf32(acc[mt][nt], af[mt], bf[nt]);
    }
    __syncthreads();   // all warps done reading Q/K before E overwrites

    // Stage E (128x64) into smem, all warps at once.
    #pragma unroll
    for (int mt = 0; mt < 2; mt++) {
        int r = wm + mt * 16 + (lane >> 2);
        #pragma unroll
        for (int nt = 0; nt < 4; nt++) {
            int lc = wn + nt * 8 + (lane & 3) * 2;
            sm.E[r][lc]         = acc[mt][nt][0];
            sm.E[r][lc + 1]     = acc[mt][nt][1];
            sm.E[r + 8][lc]     = acc[mt][nt][2];
            sm.E[r + 8][lc + 1] = acc[mt][nt][3];
        }
    }
    __syncthreads();

    // Coalesced epilogue: 16 threads per row (float4), 8 row-iterations.
    const int* mb = mask + (size_t)b * S_ * S_;
    float* ab = attn + (size_t)bh * S_ * S_;
    const int cl = (tid & 15) * 4;
    const int k = k0 + cl;
    #pragma unroll
    for (int j = 0; j < 8; j++) {
        int row = j * 16 + (tid >> 4);
        int q = q0 + row;
        float4 ev = *(float4*)&sm.E[row][cl];
        int4  mv = *(const int4*)&mb[(size_t)q * S_ + k];
        float p0 = mv.x ? tf32f(__expf(ev.x * SCALE_INV)) : 0.f;
        float p1 = mv.y ? tf32f(__expf(ev.y * SCALE_INV)) : 0.f;
        float p2 = mv.z ? tf32f(__expf(ev.z * SCALE_INV)) : 0.f;
        float p3 = mv.w ? tf32f(__expf(ev.w * SCALE_INV)) : 0.f;
        float4 pv4 = { p0, p1, p2, p3 };
        *(float4*)&ab[(size_t)q * S_ + k] = pv4;
        float v = (p0 + p1) + (p2 + p3);
        v += __shfl_xor_sync(0xffffffffu, v, 1);
        v += __shfl_xor_sync(0xffffffffu, v, 2);
        v += __shfl_xor_sync(0xffffffffu, v, 4);
        v += __shfl_xor_sync(0xffffffffu, v, 8);
        if ((tid & 15) == 0)
            psum[((size_t)bh * S_ + q) * 32 + kblk] = v;
    }
}

// ---------------------------------------------------------------------------
// PV + normalize. Tile 128(q) x 64(d), warp tile 32x32, K chunked by 32,
// 2-stage cp.async. MMA on unnormalized tf32 P; normalization at stores.
// ---------------------------------------------------------------------------
__global__ __launch_bounds__(256, 3) void pv_norm(float* __restrict__ attn,
                                                  const float* __restrict__ psum) {
    __shared__ float sP[2][128][36];
    __shared__ float sV[2][32][68];
    __shared__ float sInv[128];
    const int tid = threadIdx.x, lane = tid & 31, w = tid >> 5;
    const int wm = (w >> 1) * 32, wn = (w & 1) * 32;
    const int bh = blockIdx.y, b = bh >> 4, h = bh & 15;
    const int q0 = blockIdx.x * 128;
    float* Pb = attn + (size_t)bh * S_ * S_;
    const float* Vb = g_V + (size_t)bh * S_ * HD_;

    if (tid < 128) {
        const float* ps = psum + ((size_t)bh * S_ + q0 + tid) * 32;
        float sum = 0.f;
        #pragma unroll
        for (int i = 0; i < 32; i++) sum += ps[i];
        sInv[tid] = 1.0f / sum;
    }

    // Prefetch stage 0
    #pragma unroll
    for (int i = tid; i < 1024; i += 256) {
        int r = i >> 3, c4 = (i & 7) * 4;
        CP_ASYNC16(smaddr(&sP[0][r][c4]), &Pb[(size_t)(q0 + r) * S_ + c4]);
    }
    #pragma unroll
    for (int i = tid; i < 512; i += 256) {
        int r = i >> 4, c4 = (i & 15) * 4;
        CP_ASYNC16(smaddr(&sV[0][r][c4]), &Vb[(size_t)r * HD_ + c4]);
    }
    CP_COMMIT();

    float acc[2][4][4] = {};

    for (int it = 0; it < 64; it++) {
        const int kc = it * 32, s = it & 1;
        if (it + 1 < 64) {
            const int kn = kc + 32, sn = s ^ 1;
            #pragma unroll
            for (int i = tid; i < 1024; i += 256) {
                int r = i >> 3, c4 = (i & 7) * 4;
                CP_ASYNC16(smaddr(&sP[sn][r][c4]), &Pb[(size_t)(q0 + r) * S_ + kn + c4]);
            }
            #pragma unroll
            for (int i = tid; i < 512; i += 256) {
                int r = i >> 4, c4 = (i & 15) * 4;
                CP_ASYNC16(smaddr(&sV[sn][r][c4]), &Vb[(size_t)(kn + r) * HD_ + c4]);
            }
            CP_COMMIT();
            CP_WAIT1();
        } else {
            CP_WAIT0();
        }
        __syncthreads();

        #pragma unroll
        for (int ks = 0; ks < 4; ks++) {
            uint32_t af[2][4], bf[4][2];
            #pragma unroll
            for (int mt = 0; mt < 2; mt++) lda_frag(af[mt], &sP[s][0][0], 36, wm + mt * 16, ks * 8, lane);
            #pragma unroll
            for (int nt = 0; nt < 4; nt++) {
                const float* p = &sV[s][ks * 8 + (lane & 3)][wn + nt * 8 + (lane >> 2)];
                bf[nt][0] = __float_as_uint(p[0]);
                bf[nt][1] = __float_as_uint(p[4 * 68]);
            }
            #pragma unroll
            for (int mt = 0; mt < 2; mt++)
                #pragma unroll
                for (int nt = 0; nt < 4; nt++)
                    mma_tf32(acc[mt][nt], af[mt], bf[nt]);
        }

        // Normalized attention store for this chunk (coalesced float4).
        #pragma unroll
        for (int i = tid; i < 1024; i += 256) {
            int r = i >> 3, c4 = (i & 7) * 4;
            float inv = sInv[r];
            float4 v = *(float4*)&sP[s][r][c4];
            v.x *= inv; v.y *= inv; v.z *= inv; v.w *= inv;
            *(float4*)&Pb[(size_t)(q0 + r) * S_ + kc + c4] = v;
        }
        __syncthreads();
    }

    #pragma unroll
    for (int mt = 0; mt < 2; mt++) {
        #pragma unroll
        for (int nt = 0; nt < 4; nt++) {
            int rr = wm + mt * 16 + (lane >> 2);
            int c0 = wn + nt * 8 + (lane & 3) * 2;
            #pragma unroll
            for (int e = 0; e < 4; e++) {
                int rl = rr + (e >> 1) * 8;
                int q = q0 + rl;
                int d = c0 + (e & 1);
                g_X[((size_t)(b * S_ + q)) * H_ + h * HD_ + d] = acc[mt][nt][e] * sInv[rl];
            }
        }
    }
}

// ---------------------------------------------------------------------------
extern "C" void kernel_launch(void* const* d_in, const int* in_sizes, int n_in,
                              void* d_out, int out_size) {
    const float* query = (const float*)d_in[0];
    const float* key   = (const float*)d_in[1];
    const float* value = (const float*)d_in[2];
    const int*   mask  = (const int*)d_in[3];
    const float* Wq = (const float*)d_in[4];  const float* bq = (const float*)d_in[5];
    const float* Wk = (const float*)d_in[6];  const float* bk = (const float*)d_in[7];
    const float* Wv = (const float*)d_in[8];  const float* bv = (const float*)d_in[9];
    const float* Wo = (const float*)d_in[10]; const float* bo = (const float*)d_in[11];

    float* out  = (float*)d_out;
    float* attn = out + (size_t)B_ * S_ * H_;

    float *gQ, *gK, *gV, *gX, *gPS;
    cudaGetSymbolAddress((void**)&gQ, g_Q);
    cudaGetSymbolAddress((void**)&gK, g_K);
    cudaGetSymbolAddress((void**)&gV, g_V);
    cudaGetSymbolAddress((void**)&gX, g_X);
    cudaGetSymbolAddress((void**)&gPS, g_psum);

    dim3 grid_proj(H_ / 128, M_ / 128);        // (8, 64)
    proj_mma<<<grid_proj, 256>>>(query, Wq, bq, gQ, 1);
    proj_mma<<<grid_proj, 256>>>(key,   Wk, bk, gK, 1);
    proj_mma<<<grid_proj, 256>>>(value, Wv, bv, gV, 1);

    dim3 grid_e(S_ / 64, S_ / 128, B_ * NH_);  // (32, 16, 64)
    energy_exp<<<grid_e, 256>>>(mask, attn, gPS);

    dim3 grid_pv(S_ / 128, B_ * NH_);          // (16, 64)
    pv_norm<<<grid_pv, 256>>>(attn, gPS);

    proj_mma<<<grid_proj, 256>>>(gX, Wo, bo, out, 0);
}

// round 7
// speedup vs baseline: 5.6242x; 1.0057x over previous
#include <cuda_runtime.h>
#include <math.h>
#include <stdint.h>

#define B_  4
#define S_  2048
#define H_  1024
#define NH_ 16
#define HD_ 64
#define M_  (B_ * S_)
#define SCALE_INV 0.125f

// Scratch (device globals — no allocation allowed)
__device__ float g_Q[M_ * H_];            // [B,NH,S,HD]  tf32-rounded, pre-scaled by 1/8
__device__ float g_K[M_ * H_];            // [B,NH,S,HD]  tf32-rounded
__device__ float g_V[M_ * H_];            // [B,NH,S,HD]  tf32-rounded
__device__ float g_X[M_ * H_];            // [B,S,H]
__device__ float g_psum[64 * S_ * 32];    // [bh][q][kblock(64)] partial row sums

// ---------------------------------------------------------------------------
__device__ __forceinline__ uint32_t f2tf32(float x) {  // round-to-nearest tf32
    uint32_t r; asm("cvt.rna.tf32.f32 %0, %1;" : "=r"(r) : "f"(x)); return r;
}
__device__ __forceinline__ float tf32f(float x) { return __uint_as_float(f2tf32(x)); }

__device__ __forceinline__ void mma_tf32(float* c, const uint32_t* a, const uint32_t* b) {
    asm volatile("mma.sync.aligned.m16n8k8.row.col.f32.tf32.tf32.f32 "
        "{%0,%1,%2,%3}, {%4,%5,%6,%7}, {%8,%9}, {%0,%1,%2,%3};"
        : "+f"(c[0]), "+f"(c[1]), "+f"(c[2]), "+f"(c[3])
        : "r"(a[0]), "r"(a[1]), "r"(a[2]), "r"(a[3]), "r"(b[0]), "r"(b[1]));
}

__device__ __forceinline__ void lda_frag(uint32_t* a, const float* s, int lds,
                                         int mbase, int k, int lane) {
    const float* p = s + (size_t)(mbase + (lane >> 2)) * lds + k + (lane & 3);
    a[0] = __float_as_uint(p[0]);
    a[1] = __float_as_uint(p[8 * lds]);
    a[2] = __float_as_uint(p[4]);
    a[3] = __float_as_uint(p[8 * lds + 4]);
}
__device__ __forceinline__ void ldb_frag(uint32_t* b, const float* s, int lds,
                                         int nbase, int k, int lane) {
    const float* p = s + (size_t)(nbase + (lane >> 2)) * lds + k + (lane & 3);
    b[0] = __float_as_uint(p[0]);
    b[1] = __float_as_uint(p[4]);
}

__device__ __forceinline__ uint32_t smaddr(const void* p) {
    return (uint32_t)__cvta_generic_to_shared(p);
}
#define CP_ASYNC16(dst, src) \
    asm volatile("cp.async.cg.shared.global [%0], [%1], 16;" :: "r"(dst), "l"(src))
#define CP_COMMIT() asm volatile("cp.async.commit_group;" ::: "memory")
#define CP_WAIT0()  asm volatile("cp.async.wait_group 0;" ::: "memory")
#define CP_WAIT1()  asm volatile("cp.async.wait_group 1;" ::: "memory")

// ---------------------------------------------------------------------------
// Projection GEMM: C[m,n] = A[m,:]·W[n,:] + bias[n]. Tile 128x128, cp.async
// 2-stage, tf32 cvt applied on fragments (hidden under MMA).
// mode 0: out[m][n] fp32; mode 1: out[b,h,s,d] tf32-rounded
// mode 2: out[b,h,s,d] tf32-rounded and pre-scaled by 1/8 (Q path)
// ---------------------------------------------------------------------------
__global__ __launch_bounds__(256, 2) void proj_mma(const float* __restrict__ A,
                                                   const float* __restrict__ W,
                                                   const float* __restrict__ bias,
                                                   float* __restrict__ out, int mode) {
    __shared__ float sA[2][128][36];
    __shared__ float sB[2][128][36];
    const int tid = threadIdx.x, lane = tid & 31, w = tid >> 5;
    const int wm = (w >> 2) * 64, wn = (w & 3) * 32;
    const int m0 = blockIdx.y * 128, n0 = blockIdx.x * 128;

    float acc[4][4][4] = {};

    // Prefetch chunk 0
    #pragma unroll
    for (int i = tid; i < 1024; i += 256) {
        int r = i >> 3, c4 = (i & 7) * 4;
        CP_ASYNC16(smaddr(&sA[0][r][c4]), &A[(size_t)(m0 + r) * H_ + c4]);
        CP_ASYNC16(smaddr(&sB[0][r][c4]), &W[(size_t)(n0 + r) * H_ + c4]);
    }
    CP_COMMIT();

    for (int it = 0; it < 32; it++) {
        const int s = it & 1;
        if (it + 1 < 32) {
            const int kn = (it + 1) * 32, sn = s ^ 1;
            #pragma unroll
            for (int i = tid; i < 1024; i += 256) {
                int r = i >> 3, c4 = (i & 7) * 4;
                CP_ASYNC16(smaddr(&sA[sn][r][c4]), &A[(size_t)(m0 + r) * H_ + kn + c4]);
                CP_ASYNC16(smaddr(&sB[sn][r][c4]), &W[(size_t)(n0 + r) * H_ + kn + c4]);
            }
            CP_COMMIT();
            CP_WAIT1();
        } else {
            CP_WAIT0();
        }
        __syncthreads();

        #pragma unroll
        for (int ks = 0; ks < 4; ks++) {
            uint32_t af[4][4], bf[4][2];
            #pragma unroll
            for (int mt = 0; mt < 4; mt++) {
                lda_frag(af[mt], &sA[s][0][0], 36, wm + mt * 16, ks * 8, lane);
                #pragma unroll
                for (int j = 0; j < 4; j++) af[mt][j] = f2tf32(__uint_as_float(af[mt][j]));
            }
            #pragma unroll
            for (int nt = 0; nt < 4; nt++) {
                ldb_frag(bf[nt], &sB[s][0][0], 36, wn + nt * 8, ks * 8, lane);
                bf[nt][0] = f2tf32(__uint_as_float(bf[nt][0]));
                bf[nt][1] = f2tf32(__uint_as_float(bf[nt][1]));
            }
            #pragma unroll
            for (int mt = 0; mt < 4; mt++)
                #pragma unroll
                for (int nt = 0; nt < 4; nt++)
                    mma_tf32(acc[mt][nt], af[mt], bf[nt]);
        }
        __syncthreads();
    }

    #pragma unroll
    for (int mt = 0; mt < 4; mt++) {
        #pragma unroll
        for (int nt = 0; nt < 4; nt++) {
            int r0 = m0 + wm + mt * 16 + (lane >> 2);
            int c0 = n0 + wn + nt * 8 + (lane & 3) * 2;
            #pragma unroll
            for (int e = 0; e < 4; e++) {
                int m = r0 + (e >> 1) * 8;
                int n = c0 + (e & 1);
                float v = acc[mt][nt][e] + bias[n];
                if (mode == 0) {
                    out[(size_t)m * H_ + n] = v;
                } else {
                    int b = m >> 11, sq = m & 2047, h = n >> 6, dd = n & 63;
                    float o = tf32f(v);
                    if (mode == 2) o *= SCALE_INV;   // exact (exponent shift)
                    out[(((size_t)(b * NH_ + h) * S_) + sq) * HD_ + dd] = o;
                }
            }
        }
    }
}

// ---------------------------------------------------------------------------
// Energy + exp + mask. Tile 128(q) x 64(k). Q pre-scaled by 1/8 so E needs no
// scaling. Mask prefetched + bit-packed in the prologue (latency hidden under
// tile load + MMA). Writes tf32-rounded unnormalized P.
// ---------------------------------------------------------------------------
__global__ __launch_bounds__(256, 3) void energy_exp(const int* __restrict__ mask,
                                                     float* __restrict__ attn,
                                                     float* __restrict__ psum) {
    __shared__ union {
        struct { float A[128][68]; float B[64][68]; } ld;
        float E[128][68];
    } sm;
    const int tid = threadIdx.x, lane = tid & 31, w = tid >> 5;
    const int wm = (w >> 1) * 32, wn = (w & 1) * 32;
    const int bh = blockIdx.z, b = bh >> 4;
    const int q0 = blockIdx.y * 128, k0 = blockIdx.x * 64;
    const int kblk = blockIdx.x;
    const float* Qb = g_Q + (size_t)bh * S_ * HD_;
    const float* Kb = g_K + (size_t)bh * S_ * HD_;

    // One-shot tile loads: Q[128][64], K[64][64]
    #pragma unroll
    for (int i = tid; i < 2048; i += 256) {
        int r = i >> 4, c4 = (i & 15) * 4;
        CP_ASYNC16(smaddr(&sm.ld.A[r][c4]), &Qb[(size_t)(q0 + r) * HD_ + c4]);
    }
    #pragma unroll
    for (int i = tid; i < 1024; i += 256) {
        int r = i >> 4, c4 = (i & 15) * 4;
        CP_ASYNC16(smaddr(&sm.ld.B[r][c4]), &Kb[(size_t)(k0 + r) * HD_ + c4]);
    }
    CP_COMMIT();

    // Mask prefetch + bit-pack (latency hidden under tile load + MMA).
    const int* mb = mask + (size_t)b * S_ * S_;
    const int cl = (tid & 15) * 4;
    const int k = k0 + cl;
    uint32_t pmask = 0;
    #pragma unroll
    for (int j = 0; j < 8; j++) {
        int q = q0 + j * 16 + (tid >> 4);
        int4 mv = *(const int4*)&mb[(size_t)q * S_ + k];
        uint32_t bits = (mv.x ? 1u : 0u) | (mv.y ? 2u : 0u)
                      | (mv.z ? 4u : 0u) | (mv.w ? 8u : 0u);
        pmask |= bits << (4 * j);
    }

    CP_WAIT0();
    __syncthreads();

    float acc[2][4][4] = {};
    #pragma unroll
    for (int ks = 0; ks < 8; ks++) {
        uint32_t af[2][4], bf[4][2];
        #pragma unroll
        for (int mt = 0; mt < 2; mt++) lda_frag(af[mt], &sm.ld.A[0][0], 68, wm + mt * 16, ks * 8, lane);
        #pragma unroll
        for (int nt = 0; nt < 4; nt++) ldb_frag(bf[nt], &sm.ld.B[0][0], 68, wn + nt * 8, ks * 8, lane);
        #pragma unroll
        for (int mt = 0; mt < 2; mt++)
            #pragma unroll
            for (int nt = 0; nt < 4; nt++)
                mma_tf32(acc[mt][nt], af[mt], bf[nt]);
    }
    __syncthreads();   // all warps done reading Q/K before E overwrites

    // Stage E (128x64) into smem, all warps at once.
    #pragma unroll
    for (int mt = 0; mt < 2; mt++) {
        int r = wm + mt * 16 + (lane >> 2);
        #pragma unroll
        for (int nt = 0; nt < 4; nt++) {
            int lc = wn + nt * 8 + (lane & 3) * 2;
            sm.E[r][lc]         = acc[mt][nt][0];
            sm.E[r][lc + 1]     = acc[mt][nt][1];
            sm.E[r + 8][lc]     = acc[mt][nt][2];
            sm.E[r + 8][lc + 1] = acc[mt][nt][3];
        }
    }
    __syncthreads();

    // Coalesced epilogue: no global loads remain (mask is in pmask).
    float* ab = attn + (size_t)bh * S_ * S_;
    #pragma unroll
    for (int j = 0; j < 8; j++) {
        int row = j * 16 + (tid >> 4);
        int q = q0 + row;
        float4 ev = *(float4*)&sm.E[row][cl];
        uint32_t bits = (pmask >> (4 * j)) & 0xfu;
        float p0 = (bits & 1u) ? tf32f(__expf(ev.x)) : 0.f;
        float p1 = (bits & 2u) ? tf32f(__expf(ev.y)) : 0.f;
        float p2 = (bits & 4u) ? tf32f(__expf(ev.z)) : 0.f;
        float p3 = (bits & 8u) ? tf32f(__expf(ev.w)) : 0.f;
        float4 pv4 = { p0, p1, p2, p3 };
        *(float4*)&ab[(size_t)q * S_ + k] = pv4;
        float v = (p0 + p1) + (p2 + p3);
        v += __shfl_xor_sync(0xffffffffu, v, 1);
        v += __shfl_xor_sync(0xffffffffu, v, 2);
        v += __shfl_xor_sync(0xffffffffu, v, 4);
        v += __shfl_xor_sync(0xffffffffu, v, 8);
        if ((tid & 15) == 0)
            psum[((size_t)bh * S_ + q) * 32 + kblk] = v;
    }
}

// ---------------------------------------------------------------------------
// PV + normalize. Tile 128(q) x 64(d), warp tile 32x32, K chunked by 32,
// 2-stage cp.async. MMA on unnormalized tf32 P; normalization at stores.
// ---------------------------------------------------------------------------
__global__ __launch_bounds__(256, 3) void pv_norm(float* __restrict__ attn,
                                                  const float* __restrict__ psum) {
    __shared__ float sP[2][128][36];
    __shared__ float sV[2][32][68];
    __shared__ float sInv[128];
    const int tid = threadIdx.x, lane = tid & 31, w = tid >> 5;
    const int wm = (w >> 1) * 32, wn = (w & 1) * 32;
    const int bh = blockIdx.y, b = bh >> 4, h = bh & 15;
    const int q0 = blockIdx.x * 128;
    float* Pb = attn + (size_t)bh * S_ * S_;
    const float* Vb = g_V + (size_t)bh * S_ * HD_;

    if (tid < 128) {
        const float* ps = psum + ((size_t)bh * S_ + q0 + tid) * 32;
        float sum = 0.f;
        #pragma unroll
        for (int i = 0; i < 32; i++) sum += ps[i];
        sInv[tid] = 1.0f / sum;
    }

    // Prefetch stage 0
    #pragma unroll
    for (int i = tid; i < 1024; i += 256) {
        int r = i >> 3, c4 = (i & 7) * 4;
        CP_ASYNC16(smaddr(&sP[0][r][c4]), &Pb[(size_t)(q0 + r) * S_ + c4]);
    }
    #pragma unroll
    for (int i = tid; i < 512; i += 256) {
        int r = i >> 4, c4 = (i & 15) * 4;
        CP_ASYNC16(smaddr(&sV[0][r][c4]), &Vb[(size_t)r * HD_ + c4]);
    }
    CP_COMMIT();

    float acc[2][4][4] = {};

    for (int it = 0; it < 64; it++) {
        const int kc = it * 32, s = it & 1;
        if (it + 1 < 64) {
            const int kn = kc + 32, sn = s ^ 1;
            #pragma unroll
            for (int i = tid; i < 1024; i += 256) {
                int r = i >> 3, c4 = (i & 7) * 4;
                CP_ASYNC16(smaddr(&sP[sn][r][c4]), &Pb[(size_t)(q0 + r) * S_ + kn + c4]);
            }
            #pragma unroll
            for (int i = tid; i < 512; i += 256) {
                int r = i >> 4, c4 = (i & 15) * 4;
                CP_ASYNC16(smaddr(&sV[sn][r][c4]), &Vb[(size_t)(kn + r) * HD_ + c4]);
            }
            CP_COMMIT();
            CP_WAIT1();
        } else {
            CP_WAIT0();
        }
        __syncthreads();

        #pragma unroll
        for (int ks = 0; ks < 4; ks++) {
            uint32_t af[2][4], bf[4][2];
            #pragma unroll
            for (int mt = 0; mt < 2; mt++) lda_frag(af[mt], &sP[s][0][0], 36, wm + mt * 16, ks * 8, lane);
            #pragma unroll
            for (int nt = 0; nt < 4; nt++) {
                const float* p = &sV[s][ks * 8 + (lane & 3)][wn + nt * 8 + (lane >> 2)];
                bf[nt][0] = __float_as_uint(p[0]);
                bf[nt][1] = __float_as_uint(p[4 * 68]);
            }
            #pragma unroll
            for (int mt = 0; mt < 2; mt++)
                #pragma unroll
                for (int nt = 0; nt < 4; nt++)
                    mma_tf32(acc[mt][nt], af[mt], bf[nt]);
        }

        // Normalized attention store for this chunk (coalesced float4).
        #pragma unroll
        for (int i = tid; i < 1024; i += 256) {
            int r = i >> 3, c4 = (i & 7) * 4;
            float inv = sInv[r];
            float4 v = *(float4*)&sP[s][r][c4];
            v.x *= inv; v.y *= inv; v.z *= inv; v.w *= inv;
            *(float4*)&Pb[(size_t)(q0 + r) * S_ + kc + c4] = v;
        }
        __syncthreads();
    }

    #pragma unroll
    for (int mt = 0; mt < 2; mt++) {
        #pragma unroll
        for (int nt = 0; nt < 4; nt++) {
            int rr = wm + mt * 16 + (lane >> 2);
            int c0 = wn + nt * 8 + (lane & 3) * 2;
            #pragma unroll
            for (int e = 0; e < 4; e++) {
                int rl = rr + (e >> 1) * 8;
                int q = q0 + rl;
                int d = c0 + (e & 1);
                g_X[((size_t)(b * S_ + q)) * H_ + h * HD_ + d] = acc[mt][nt][e] * sInv[rl];
            }
        }
    }
}

// ---------------------------------------------------------------------------
extern "C" void kernel_launch(void* const* d_in, const int* in_sizes, int n_in,
                              void* d_out, int out_size) {
    const float* query = (const float*)d_in[0];
    const float* key   = (const float*)d_in[1];
    const float* value = (const float*)d_in[2];
    const int*   mask  = (const int*)d_in[3];
    const float* Wq = (const float*)d_in[4];  const float* bq = (const float*)d_in[5];
    const float* Wk = (const float*)d_in[6];  const float* bk = (const float*)d_in[7];
    const float* Wv = (const float*)d_in[8];  const float* bv = (const float*)d_in[9];
    const float* Wo = (const float*)d_in[10]; const float* bo = (const float*)d_in[11];

    float* out  = (float*)d_out;
    float* attn = out + (size_t)B_ * S_ * H_;

    float *gQ, *gK, *gV, *gX, *gPS;
    cudaGetSymbolAddress((void**)&gQ, g_Q);
    cudaGetSymbolAddress((void**)&gK, g_K);
    cudaGetSymbolAddress((void**)&gV, g_V);
    cudaGetSymbolAddress((void**)&gX, g_X);
    cudaGetSymbolAddress((void**)&gPS, g_psum);

    dim3 grid_proj(H_ / 128, M_ / 128);        // (8, 64)
    proj_mma<<<grid_proj, 256>>>(query, Wq, bq, gQ, 2);   // Q pre-scaled 1/8
    proj_mma<<<grid_proj, 256>>>(key,   Wk, bk, gK, 1);
    proj_mma<<<grid_proj, 256>>>(value, Wv, bv, gV, 1);

    dim3 grid_e(S_ / 64, S_ / 128, B_ * NH_);  // (32, 16, 64)
    energy_exp<<<grid_e, 256>>>(mask, attn, gPS);

    dim3 grid_pv(S_ / 128, B_ * NH_);          // (16, 64)
    pv_norm<<<grid_pv, 256>>>(attn, gPS);

    proj_mma<<<grid_proj, 256>>>(gX, Wo, bo, out, 0);
}